// round 3
// baseline (speedup 1.0000x reference)
#include <cuda_runtime.h>

// GRUConv3d: 8-direction 3D GRU with 3 conv gates per direction.
// Shapes: x (2,32,32,32,32) f32; W* (8,32,32,3,3,3); b* (8,32); h0 (8,32).
// out (2,32,32,32,32) f32.
//
// Pipeline:
//   conv_kernel    : all 8 dirs x 3 gates -> g_hb (linear+bias), g_z/g_s (sigmoid)
//   scan_kernel    : diagonal GRU recurrence per dir; overwrites g_hb with O*s
//   combine_kernel : out = sum over dirs of contrib

#define NDIR 8
#define B_   2
#define C_   32
#define SPAT 32768                      // 32*32*32
#define NT   (NDIR * B_ * C_ * SPAT)    // 16,777,216 floats per tensor

__device__ float g_hb[NT];   // conv-h output, later overwritten with contrib = O*s
__device__ float g_z [NT];   // sigmoid(conv-z)
__device__ float g_s [NT];   // sigmoid(conv-s)

// ---------------------------------------------------------------------------
// Conv kernel: each block handles (dir n, batch b, depth d, h-tile of 8 rows),
// producing 96 output channels (3 gates x 32 cout) over 8h x 32w positions.
// Register blocking: thread = (warp -> 4 couts) x (lane -> w column, 8 h rows).
// cin is chunked by 4 so that Xs + Wsm fit in static (<48KB) shared memory.
// ---------------------------------------------------------------------------
__global__ __launch_bounds__(256, 2)
void conv_kernel(const float* __restrict__ x,
                 const float* __restrict__ Wh, const float* __restrict__ bh,
                 const float* __restrict__ Wz, const float* __restrict__ bz,
                 const float* __restrict__ Ws, const float* __restrict__ bs)
{
    __shared__ float Xs[4 * 3 * 10 * 34];   // [ci4][td][hh 0..9][ww 0..33] = 16320 B
    __shared__ float Wsm[32 * 4 * 27];      // [co][ci4][tap]               = 13824 B

    const int bi  = blockIdx.x;
    const int n   = bi >> 8;          // direction
    const int rem = bi & 255;
    const int b   = rem >> 7;
    const int d   = (rem >> 2) & 31;
    const int h0  = (rem & 3) * 8;

    const int tid = threadIdx.x;
    const int cg  = tid >> 5;         // warp id: co base = cg*4
    const int sg  = tid & 31;         // w coordinate

    const float* xb = x + (size_t)b * (32 * SPAT);

    for (int gate = 0; gate < 3; gate++) {
        const float* Wg = (gate == 0) ? Wh : (gate == 1) ? Wz : Ws;

        float acc[4][8];
        #pragma unroll
        for (int c = 0; c < 4; c++)
            #pragma unroll
            for (int r = 0; r < 8; r++) acc[c][r] = 0.f;

        for (int cc = 0; cc < 8; cc++) {          // cin chunks of 4
            __syncthreads();
            // ---- stage x chunk into smem (zero-padded halo in d,h,w) ----
            for (int idx = tid; idx < 4 * 3 * 10 * 34; idx += 256) {
                int ww = idx % 34;
                int t  = idx / 34;
                int hh = t % 10; t /= 10;
                int td = t % 3;
                int ci = t / 3;
                int gd = d - 1 + td;
                int gh = h0 - 1 + hh;
                int gw = ww - 1;
                float v = 0.f;
                if ((unsigned)gd < 32u && (unsigned)gh < 32u && (unsigned)gw < 32u)
                    v = xb[(size_t)(cc * 4 + ci) * SPAT + gd * 1024 + gh * 32 + gw];
                Xs[idx] = v;
            }
            // ---- stage weight chunk: [co 0..31][ci4][tap 0..26] ----
            for (int idx = tid; idx < 32 * 4 * 27; idx += 256) {
                int tap = idx % 27;
                int t   = idx / 27;
                int ci  = t & 3;
                int co  = t >> 2;
                Wsm[idx] = Wg[(((size_t)n * 32 + co) * 32 + (cc * 4 + ci)) * 27 + tap];
            }
            __syncthreads();

            // ---- compute: 4 cin x 27 taps x (4 cout x 8 h) FMAs ----
            for (int ci = 0; ci < 4; ci++) {
                const float* Xp = Xs + ci * (3 * 10 * 34);
                const float* Wp = Wsm + (cg * 4) * (4 * 27) + ci * 27;
                for (int td = 0; td < 3; td++) {
                    for (int th = 0; th < 3; th++) {
                        const float* xr = Xp + td * 340 + th * 34 + sg;
                        const float* wr = Wp + (td * 3 + th) * 3;
                        #pragma unroll
                        for (int tw = 0; tw < 3; tw++) {
                            float w0 = wr[0 * 108 + tw];
                            float w1 = wr[1 * 108 + tw];
                            float w2 = wr[2 * 108 + tw];
                            float w3 = wr[3 * 108 + tw];
                            #pragma unroll
                            for (int r = 0; r < 8; r++) {
                                float xv = xr[r * 34 + tw];
                                acc[0][r] = fmaf(w0, xv, acc[0][r]);
                                acc[1][r] = fmaf(w1, xv, acc[1][r]);
                                acc[2][r] = fmaf(w2, xv, acc[2][r]);
                                acc[3][r] = fmaf(w3, xv, acc[3][r]);
                            }
                        }
                    }
                }
            }
        }

        // ---- epilogue: bias (+ sigmoid for z,s gates), write scratch ----
        const float* bg = (gate == 0) ? bh : (gate == 1) ? bz : bs;
        float* og       = (gate == 0) ? g_hb : (gate == 1) ? g_z : g_s;
        #pragma unroll
        for (int c = 0; c < 4; c++) {
            int   co   = cg * 4 + c;
            float bias = bg[n * 32 + co];
            float* op  = og + ((size_t)((n * 2 + b) * 32 + co)) * SPAT
                            + d * 1024 + h0 * 32 + sg;
            #pragma unroll
            for (int r = 0; r < 8; r++) {
                float v = acc[c][r] + bias;
                if (gate > 0) v = 1.f / (1.f + __expf(-v));
                op[r * 32] = v;
            }
        }
    }
}

// ---------------------------------------------------------------------------
// Scan kernel: one thread per diagonal chain. Chain starts live on the 3
// "entry" faces of the cube for direction (di,dj,dk). Each cell is visited
// exactly once; contrib = O*s overwrites g_hb in place (no races).
// 2977 chains per (dir,b,c) -> 3 blocks of 1024 threads.
// ---------------------------------------------------------------------------
__global__ void scan_kernel(const float* __restrict__ h0)
{
    int bid  = blockIdx.x;
    int part = bid % 3;
    int t    = bid / 3;
    int c = t & 31; t >>= 5;
    int b = t & 1;
    int n = t >> 1;

    int cid = part * 1024 + threadIdx.x;
    if (cid >= 2977) return;

    const int di = (n & 4) ? 1 : -1;
    const int dj = (n & 2) ? 1 : -1;
    const int dk = (n & 1) ? 1 : -1;
    const int si = (di == 1) ? 0 : 31;
    const int sj = (dj == 1) ? 0 : 31;
    const int sk = (dk == 1) ? 0 : 31;

    int i0, j0, k0;
    if (cid < 1024) {                       // face i == si (1024 chains)
        i0 = si; j0 = cid >> 5; k0 = cid & 31;
    } else if (cid < 2016) {                // face j == sj, i != si (992)
        int q = cid - 1024;
        j0 = sj;
        int ii = q >> 5;
        i0 = (di == 1) ? ii + 1 : ii;
        k0 = q & 31;
    } else {                                // face k == sk, i != si, j != sj (961)
        int q = cid - 2016;
        k0 = sk;
        int ii = q / 31;
        int jj = q % 31;
        i0 = (di == 1) ? ii + 1 : ii;
        j0 = (dj == 1) ? jj + 1 : jj;
    }

    int li = (di == 1) ? 32 - i0 : i0 + 1;
    int lj = (dj == 1) ? 32 - j0 : j0 + 1;
    int lk = (dk == 1) ? 32 - k0 : k0 + 1;
    int L  = min(li, min(lj, lk));

    const size_t base = ((size_t)((n * 2 + b) * 32 + c)) << 15;
    int idx  = i0 * 1024 + j0 * 32 + k0;
    int step = di * 1024 + dj * 32 + dk;

    float h = h0[n * 32 + c];
    for (int s = 0; s < L; s++, idx += step) {
        float zv = g_z [base + idx];
        float hv = g_hb[base + idx];
        float sv = g_s [base + idx];
        h = fmaf(zv, hv - h, h);            // z*hb + (1-z)*h
        g_hb[base + idx] = h * sv;          // contrib, in place
    }
}

// ---------------------------------------------------------------------------
// Combine: out[b,c,spatial] = sum over 8 dirs of contrib
// ---------------------------------------------------------------------------
__global__ void combine_kernel(float* __restrict__ out)
{
    int p = blockIdx.x * blockDim.x + threadIdx.x;
    if (p >= B_ * C_ * SPAT) return;
    int sp = p & (SPAT - 1);
    int t  = p >> 15;
    int c  = t & 31;
    int b  = t >> 5;
    float s = 0.f;
    #pragma unroll
    for (int n = 0; n < 8; n++)
        s += g_hb[((size_t)((n * 2 + b) * 32 + c) << 15) + sp];
    out[p] = s;
}

extern "C" void kernel_launch(void* const* d_in, const int* in_sizes, int n_in,
                              void* d_out, int out_size)
{
    const float* x  = (const float*)d_in[0];
    const float* Wh = (const float*)d_in[1];
    const float* bh = (const float*)d_in[2];
    const float* Wz = (const float*)d_in[3];
    const float* bz = (const float*)d_in[4];
    const float* Ws = (const float*)d_in[5];
    const float* bs = (const float*)d_in[6];
    const float* h0 = (const float*)d_in[7];
    float* out = (float*)d_out;

    conv_kernel<<<2048, 256>>>(x, Wh, bh, Wz, bz, Ws, bs);
    scan_kernel<<<1536, 1024>>>(h0);
    combine_kernel<<<(B_ * C_ * SPAT + 255) / 256, 256>>>(out);
}